// round 6
// baseline (speedup 1.0000x reference)
#include <cuda_runtime.h>
#include <cuda_bf16.h>
#include <cuda_fp16.h>
#include <cstdint>
#include <cstddef>

// Problem dims (fixed)
#define B_   2
#define NP_  512
#define NC_  512
#define D_   128
#define P_   128

// ---------------- device scratch (allocation-free) ----------------
__device__ __align__(16) float  g_pn[(size_t)B_ * NP_ * D_];   // layernormed p, fp32
__device__ __align__(16) __half g_ch[(size_t)B_ * NC_ * D_];   // layernormed c, fp16

__device__ __forceinline__ uint32_t smem_u32(const void* p) {
    uint32_t a;
    asm("{ .reg .u64 t; cvta.to.shared.u64 t, %1; cvt.u32.u64 %0, t; }"
        : "=r"(a) : "l"(p));
    return a;
}

// ---------------- SMEM layout ----------------
#define LDA      272                      // 128 fp16 = 256B + 16B pad
#define SM_P     0                        // 512 B
#define SM_BIAS  512                      // 512 B
#define SM_SCALE 1024                     // 512 floats = 2048 B
#define SM_A     3072
#define SM_BHI   (SM_A   + 128 * LDA)
#define SM_BLO   (SM_BHI + 128 * LDA)
#define SM_TOTAL (SM_BLO + 128 * LDA)     // 107520 bytes -> 2 CTAs/SM

// ---------------------------------------------------------------------------
// LayerNorm: one warp per row. p rows -> fp32; c rows -> fp16.
// ---------------------------------------------------------------------------
__global__ void ln_kernel(const float* __restrict__ p_in,
                          const float* __restrict__ c_in,
                          const float* __restrict__ pw, const float* __restrict__ pb,
                          const float* __restrict__ cw, const float* __restrict__ cb) {
    int gwarp = (blockIdx.x * blockDim.x + threadIdx.x) >> 5;
    int lane  = threadIdx.x & 31;
    if (gwarp >= B_ * (NP_ + NC_)) return;

    bool is_p = gwarp < B_ * NP_;
    int row = is_p ? gwarp : gwarp - B_ * NP_;
    const float* src = is_p ? p_in : c_in;
    const float* w   = is_p ? pw : cw;
    const float* bb  = is_p ? pb : cb;

    float4 v = reinterpret_cast<const float4*>(src + (size_t)row * D_)[lane];

    float s = v.x + v.y + v.z + v.w;
    #pragma unroll
    for (int o = 16; o > 0; o >>= 1) s += __shfl_xor_sync(0xFFFFFFFFu, s, o);
    float mu = s * (1.0f / D_);

    float dx = v.x - mu, dy = v.y - mu, dz = v.z - mu, dw = v.w - mu;
    float q = dx * dx + dy * dy + dz * dz + dw * dw;
    #pragma unroll
    for (int o = 16; o > 0; o >>= 1) q += __shfl_xor_sync(0xFFFFFFFFu, q, o);
    float inv = rsqrtf(q * (1.0f / D_) + 1e-5f);

    float4 wv = reinterpret_cast<const float4*>(w)[lane];
    float4 bv = reinterpret_cast<const float4*>(bb)[lane];
    float o0 = dx * inv * wv.x + bv.x;
    float o1 = dy * inv * wv.y + bv.y;
    float o2 = dz * inv * wv.z + bv.z;
    float o3 = dw * inv * wv.w + bv.w;

    if (is_p) {
        float4 o4 = {o0, o1, o2, o3};
        reinterpret_cast<float4*>(g_pn + (size_t)row * D_)[lane] = o4;
    } else {
        __half2 h01 = __floats2half2_rn(o0, o1);
        __half2 h23 = __floats2half2_rn(o2, o3);
        uint2 hw;
        hw.x = *reinterpret_cast<uint32_t*>(&h01);
        hw.y = *reinterpret_cast<uint32_t*>(&h23);
        reinterpret_cast<uint2*>(g_ch + (size_t)row * D_)[lane] = hw;
    }
}

// ---------------------------------------------------------------------------
// Asymmetric-split fp16 warp-MMA interaction kernel, i-persistent.
// Grid (i=512, b=2), 128 threads = 4 warps in 2(m) x 2(n), warp tile 64x64.
// Per CTA: build B = (W o p_i) hi/lo once, then loop 4 j-tiles; A tile
// prefetched via cp.async overlapping the previous tile's epilogue.
// ---------------------------------------------------------------------------
__global__ __launch_bounds__(128, 2)
void gemm_mma_kernel(const int* __restrict__ p_mask,
                     const int* __restrict__ c_mask,
                     const float* __restrict__ W,
                     const float* __restrict__ bias,
                     float* __restrict__ out) {
    extern __shared__ char smem[];
    const uint32_t sb = smem_u32(smem);
    float* p_s     = reinterpret_cast<float*>(smem + SM_P);
    float* bias_s  = reinterpret_cast<float*>(smem + SM_BIAS);
    float* scale_s = reinterpret_cast<float*>(smem + SM_SCALE);

    const int i = blockIdx.x;
    const int b = blockIdx.y;
    const int t = threadIdx.x;
    const int wid  = t >> 5;
    const int lane = t & 31;

    // --- cp.async A tile 0 first (no smem dependencies) ---
    #pragma unroll 4
    for (int idx = t; idx < 2048; idx += 128) {
        int row = idx >> 4;
        int c16 = idx & 15;
        uint32_t dst = sb + SM_A + row * LDA + c16 * 16;
        const __half* src = g_ch + ((size_t)b * NC_ + row) * D_ + c16 * 8;
        asm volatile("cp.async.cg.shared.global [%0], [%1], 16;"
                     :: "r"(dst), "l"(src) : "memory");
    }

    // --- small loads: p row, bias, mask scales (all 512 j) ---
    if (t < 32) {
        float4 v = reinterpret_cast<const float4*>(g_pn + ((size_t)b * NP_ + i) * D_)[t];
        p_s[t * 4 + 0] = v.x; p_s[t * 4 + 1] = v.y;
        p_s[t * 4 + 2] = v.z; p_s[t * 4 + 3] = v.w;
    } else if (t < 64) {
        reinterpret_cast<float4*>(bias_s)[t - 32] =
            reinterpret_cast<const float4*>(bias)[t - 32];
    }
    {
        const bool pm = p_mask[b * NP_ + i] != 0;
        const int4 cm = reinterpret_cast<const int4*>(c_mask + b * NC_)[t];
        float4 sc;
        sc.x = (pm && cm.x) ? 1.0f : 0.0f;
        sc.y = (pm && cm.y) ? 1.0f : 0.0f;
        sc.z = (pm && cm.z) ? 1.0f : 0.0f;
        sc.w = (pm && cm.w) ? 1.0f : 0.0f;
        reinterpret_cast<float4*>(scale_s)[t] = sc;
    }
    __syncthreads();   // p_s visible

    // --- Build B = W o p_i, split fp16 hi/lo (once per CTA) ---
    #pragma unroll 4
    for (int u = t; u < 4096; u += 128) {
        int row = u >> 5;          // h
        int q   = u & 31;          // float4 index
        float4 w4 = reinterpret_cast<const float4*>(W + (size_t)row * D_)[q];
        int k = q * 4;
        float v0 = w4.x * p_s[k + 0];
        float v1 = w4.y * p_s[k + 1];
        float v2 = w4.z * p_s[k + 2];
        float v3 = w4.w * p_s[k + 3];
        __half2 h01 = __floats2half2_rn(v0, v1);
        __half2 h23 = __floats2half2_rn(v2, v3);
        float2 f01 = __half22float2(h01);
        float2 f23 = __half22float2(h23);
        __half2 l01 = __floats2half2_rn(v0 - f01.x, v1 - f01.y);
        __half2 l23 = __floats2half2_rn(v2 - f23.x, v3 - f23.y);
        uint2 hw, lw;
        hw.x = *reinterpret_cast<uint32_t*>(&h01);
        hw.y = *reinterpret_cast<uint32_t*>(&h23);
        lw.x = *reinterpret_cast<uint32_t*>(&l01);
        lw.y = *reinterpret_cast<uint32_t*>(&l23);
        *reinterpret_cast<uint2*>(smem + SM_BHI + row * LDA + k * 2) = hw;
        *reinterpret_cast<uint2*>(smem + SM_BLO + row * LDA + k * 2) = lw;
    }
    asm volatile("cp.async.wait_all;" ::: "memory");
    __syncthreads();

    const int wm = wid & 1;      // m: 64 j-rows each
    const int wn = wid >> 1;     // n: 64 h-cols each

    const uint32_t a_lane = (uint32_t)((wm * 64 + (lane & 15)) * LDA + (lane >> 4) * 16);
    const uint32_t b_lane = (uint32_t)((wn * 64 + (lane & 15)) * LDA + (lane >> 4) * 16);
    const uint32_t abase  = sb + SM_A   + a_lane;
    const uint32_t bhbase = sb + SM_BHI + b_lane;
    const uint32_t blbase = sb + SM_BLO + b_lane;

    const int g   = lane >> 2;
    const int tig = lane & 3;

    #pragma unroll 1
    for (int jt = 0; jt < 4; jt++) {
        const int j0 = jt * 128;

        // --- Mainloop: warp tile 64x64, fused hi+lo accumulation ---
        float acc[4][8][4];
        #pragma unroll
        for (int mf = 0; mf < 4; mf++)
            #pragma unroll
            for (int nf = 0; nf < 8; nf++)
                #pragma unroll
                for (int r = 0; r < 4; r++) acc[mf][nf][r] = 0.0f;

        #pragma unroll
        for (int ks = 0; ks < 8; ks++) {
            uint32_t ar[4][4];
            uint32_t bh[4][4];
            uint32_t bl[4][4];
            #pragma unroll
            for (int mf = 0; mf < 4; mf++) {
                uint32_t addr = abase + mf * (16 * LDA) + ks * 32;
                asm volatile("ldmatrix.sync.aligned.m8n8.x4.shared.b16 {%0,%1,%2,%3}, [%4];"
                             : "=r"(ar[mf][0]), "=r"(ar[mf][1]),
                               "=r"(ar[mf][2]), "=r"(ar[mf][3]) : "r"(addr));
            }
            #pragma unroll
            for (int np = 0; np < 4; np++) {
                uint32_t addr = bhbase + np * (16 * LDA) + ks * 32;
                asm volatile("ldmatrix.sync.aligned.m8n8.x4.shared.b16 {%0,%1,%2,%3}, [%4];"
                             : "=r"(bh[np][0]), "=r"(bh[np][1]),
                               "=r"(bh[np][2]), "=r"(bh[np][3]) : "r"(addr));
            }
            #pragma unroll
            for (int np = 0; np < 4; np++) {
                uint32_t addr = blbase + np * (16 * LDA) + ks * 32;
                asm volatile("ldmatrix.sync.aligned.m8n8.x4.shared.b16 {%0,%1,%2,%3}, [%4];"
                             : "=r"(bl[np][0]), "=r"(bl[np][1]),
                               "=r"(bl[np][2]), "=r"(bl[np][3]) : "r"(addr));
            }
            #pragma unroll
            for (int mf = 0; mf < 4; mf++) {
                #pragma unroll
                for (int np = 0; np < 4; np++) {
                    #pragma unroll
                    for (int sel = 0; sel < 2; sel++) {
                        const int nf = np * 2 + sel;
                        asm volatile(
                            "mma.sync.aligned.m16n8k16.row.col.f32.f16.f16.f32 "
                            "{%0,%1,%2,%3}, {%4,%5,%6,%7}, {%8,%9}, {%0,%1,%2,%3};"
                            : "+f"(acc[mf][nf][0]), "+f"(acc[mf][nf][1]),
                              "+f"(acc[mf][nf][2]), "+f"(acc[mf][nf][3])
                            : "r"(ar[mf][0]), "r"(ar[mf][1]), "r"(ar[mf][2]), "r"(ar[mf][3]),
                              "r"(bh[np][sel]), "r"(bh[np][2 + sel]));
                        asm volatile(
                            "mma.sync.aligned.m16n8k16.row.col.f32.f16.f16.f32 "
                            "{%0,%1,%2,%3}, {%4,%5,%6,%7}, {%8,%9}, {%0,%1,%2,%3};"
                            : "+f"(acc[mf][nf][0]), "+f"(acc[mf][nf][1]),
                              "+f"(acc[mf][nf][2]), "+f"(acc[mf][nf][3])
                            : "r"(ar[mf][0]), "r"(ar[mf][1]), "r"(ar[mf][2]), "r"(ar[mf][3]),
                              "r"(bl[np][sel]), "r"(bl[np][2 + sel]));
                    }
                }
            }
        }
        __syncthreads();   // all warps done reading A tile jt

        // --- Prefetch A tile jt+1 (overlaps epilogue) ---
        if (jt < 3) {
            const int j0n = (jt + 1) * 128;
            #pragma unroll 4
            for (int idx = t; idx < 2048; idx += 128) {
                int row = idx >> 4;
                int c16 = idx & 15;
                uint32_t dst = sb + SM_A + row * LDA + c16 * 16;
                const __half* src = g_ch + ((size_t)b * NC_ + j0n + row) * D_ + c16 * 8;
                asm volatile("cp.async.cg.shared.global [%0], [%1], 16;"
                             :: "r"(dst), "l"(src) : "memory");
            }
        }

        // --- Epilogue: bias + mask, fp32 stores ---
        #pragma unroll
        for (int mf = 0; mf < 4; mf++) {
            const int jl = j0 + wm * 64 + mf * 16 + g;
            const float s0 = scale_s[jl];
            const float s1 = scale_s[jl + 8];
            float* r0p = out + (((size_t)b * NP_ + i) * NC_ + jl) * P_ + wn * 64 + tig * 2;
            float* r1p = r0p + (size_t)8 * P_;
            #pragma unroll
            for (int nf = 0; nf < 8; nf++) {
                const int h = wn * 64 + nf * 8 + tig * 2;
                float2 v0, v1;
                v0.x = (acc[mf][nf][0] + bias_s[h])     * s0;
                v0.y = (acc[mf][nf][1] + bias_s[h + 1]) * s0;
                v1.x = (acc[mf][nf][2] + bias_s[h])     * s1;
                v1.y = (acc[mf][nf][3] + bias_s[h + 1]) * s1;
                *reinterpret_cast<float2*>(r0p + nf * 8) = v0;
                *reinterpret_cast<float2*>(r1p + nf * 8) = v1;
            }
        }

        asm volatile("cp.async.wait_all;" ::: "memory");
        __syncthreads();
    }
}

// ---------------------------------------------------------------------------
// inter_mask second-output kernels
// ---------------------------------------------------------------------------
__global__ void mask_float_kernel(const int* __restrict__ p_mask,
                                  const int* __restrict__ c_mask,
                                  float* __restrict__ out, long n) {
    long idx = (long)blockIdx.x * blockDim.x + threadIdx.x;
    if (idx >= n) return;
    int j  = (int)(idx & (NC_ - 1));
    long bi = idx >> 9;
    int i  = (int)(bi & (NP_ - 1));
    int b  = (int)(bi >> 9);
    out[idx] = (p_mask[b * NP_ + i] && c_mask[b * NC_ + j]) ? 1.0f : 0.0f;
}
__global__ void mask_byte_kernel(const int* __restrict__ p_mask,
                                 const int* __restrict__ c_mask,
                                 unsigned char* __restrict__ out, long n) {
    long idx = (long)blockIdx.x * blockDim.x + threadIdx.x;
    if (idx >= n) return;
    int j  = (int)(idx & (NC_ - 1));
    long bi = idx >> 9;
    int i  = (int)(bi & (NP_ - 1));
    int b  = (int)(bi >> 9);
    out[idx] = (p_mask[b * NP_ + i] && c_mask[b * NC_ + j]) ? 1 : 0;
}

// ---------------------------------------------------------------------------
extern "C" void kernel_launch(void* const* d_in, const int* in_sizes, int n_in,
                              void* d_out, int out_size) {
    const float* p_embed = (const float*)d_in[0];
    const float* c_embed = (const float*)d_in[1];
    const int*   p_mask  = (const int*)d_in[2];
    const int*   c_mask  = (const int*)d_in[3];
    const float* ln_p_w  = (const float*)d_in[4];
    const float* ln_p_b  = (const float*)d_in[5];
    const float* ln_c_w  = (const float*)d_in[6];
    const float* ln_c_b  = (const float*)d_in[7];
    const float* W_out   = (const float*)d_in[8];
    const float* b_out   = (const float*)d_in[9];
    float* out = (float*)d_out;

    cudaFuncSetAttribute(gemm_mma_kernel,
                         cudaFuncAttributeMaxDynamicSharedMemorySize, SM_TOTAL);

    // LayerNorm (p -> fp32, c -> fp16)
    ln_kernel<<<(B_ * (NP_ + NC_)) / 8, 256>>>(p_embed, c_embed,
                                               ln_p_w, ln_p_b, ln_c_w, ln_c_b);

    // i-persistent asymmetric-split fp16 tensor-core interaction GEMM
    dim3 grid(NP_, B_);
    gemm_mma_kernel<<<grid, 128, SM_TOTAL>>>(p_mask, c_mask, W_out, b_out, out);

    // Second output tail (inter_mask), format-adaptive
    const long inter_elems = (long)B_ * NP_ * NC_ * P_;
    const long mask_elems  = (long)B_ * NP_ * NC_;
    long extra = (long)out_size - inter_elems;
    if (extra == mask_elems / 4) {
        mask_byte_kernel<<<(int)((mask_elems + 255) / 256), 256>>>(
            p_mask, c_mask, (unsigned char*)(out + inter_elems), mask_elems);
    } else if (extra > 0) {
        long n = extra < mask_elems ? extra : mask_elems;
        mask_float_kernel<<<(int)((n + 255) / 256), 256>>>(
            p_mask, c_mask, out + inter_elems, n);
    }
}

// round 7
// speedup vs baseline: 1.3663x; 1.3663x over previous
#include <cuda_runtime.h>
#include <cuda_bf16.h>
#include <cuda_fp16.h>
#include <cstdint>
#include <cstddef>

// Problem dims (fixed)
#define B_   2
#define NP_  512
#define NC_  512
#define D_   128
#define P_   128

// ---------------- device scratch (allocation-free) ----------------
__device__ __align__(16) float  g_pn[(size_t)B_ * NP_ * D_];   // layernormed p, fp32
__device__ __align__(16) __half g_ch[(size_t)B_ * NC_ * D_];   // layernormed c, fp16

__device__ __forceinline__ uint32_t smem_u32(const void* p) {
    uint32_t a;
    asm("{ .reg .u64 t; cvta.to.shared.u64 t, %1; cvt.u32.u64 %0, t; }"
        : "=r"(a) : "l"(p));
    return a;
}

// ---------------- SMEM layout ----------------
#define LDA      272                      // 128 fp16 = 256B + 16B pad
#define SM_P     0                        // 512 B
#define SM_BIAS  512                      // 512 B
#define SM_SCALE 1024                     // 512 floats = 2048 B
#define SM_A     3072
#define SM_BHI   (SM_A + 128 * LDA)
#define SM_TOTAL (SM_BHI + 128 * LDA)     // 72704 bytes -> 2 CTAs/SM easily

// ---------------------------------------------------------------------------
// LayerNorm: one warp per row. p rows -> fp32; c rows -> fp16.
// ---------------------------------------------------------------------------
__global__ void ln_kernel(const float* __restrict__ p_in,
                          const float* __restrict__ c_in,
                          const float* __restrict__ pw, const float* __restrict__ pb,
                          const float* __restrict__ cw, const float* __restrict__ cb) {
    int gwarp = (blockIdx.x * blockDim.x + threadIdx.x) >> 5;
    int lane  = threadIdx.x & 31;
    if (gwarp >= B_ * (NP_ + NC_)) return;

    bool is_p = gwarp < B_ * NP_;
    int row = is_p ? gwarp : gwarp - B_ * NP_;
    const float* src = is_p ? p_in : c_in;
    const float* w   = is_p ? pw : cw;
    const float* bb  = is_p ? pb : cb;

    float4 v = reinterpret_cast<const float4*>(src + (size_t)row * D_)[lane];

    float s = v.x + v.y + v.z + v.w;
    #pragma unroll
    for (int o = 16; o > 0; o >>= 1) s += __shfl_xor_sync(0xFFFFFFFFu, s, o);
    float mu = s * (1.0f / D_);

    float dx = v.x - mu, dy = v.y - mu, dz = v.z - mu, dw = v.w - mu;
    float q = dx * dx + dy * dy + dz * dz + dw * dw;
    #pragma unroll
    for (int o = 16; o > 0; o >>= 1) q += __shfl_xor_sync(0xFFFFFFFFu, q, o);
    float inv = rsqrtf(q * (1.0f / D_) + 1e-5f);

    float4 wv = reinterpret_cast<const float4*>(w)[lane];
    float4 bv = reinterpret_cast<const float4*>(bb)[lane];
    float o0 = dx * inv * wv.x + bv.x;
    float o1 = dy * inv * wv.y + bv.y;
    float o2 = dz * inv * wv.z + bv.z;
    float o3 = dw * inv * wv.w + bv.w;

    if (is_p) {
        float4 o4 = {o0, o1, o2, o3};
        reinterpret_cast<float4*>(g_pn + (size_t)row * D_)[lane] = o4;
    } else {
        __half2 h01 = __floats2half2_rn(o0, o1);
        __half2 h23 = __floats2half2_rn(o2, o3);
        uint2 hw;
        hw.x = *reinterpret_cast<uint32_t*>(&h01);
        hw.y = *reinterpret_cast<uint32_t*>(&h23);
        reinterpret_cast<uint2*>(g_ch + (size_t)row * D_)[lane] = hw;
    }
}

// ---------------------------------------------------------------------------
// Single-pass fp16 warp-MMA interaction kernel, i-persistent.
// Grid (i=512, b=2), 128 threads = 4 warps in 2(m) x 2(n), warp tile 64x64.
// out = A(fp16) @ B(fp16)^T in fp32 accum; A = c_ln, B = W o p_i (both
// fp16-rounded once). Error budget calibrated from R5: ~2.9e-4 << 1e-3.
// ---------------------------------------------------------------------------
__global__ __launch_bounds__(128, 2)
void gemm_mma_kernel(const int* __restrict__ p_mask,
                     const int* __restrict__ c_mask,
                     const float* __restrict__ W,
                     const float* __restrict__ bias,
                     float* __restrict__ out) {
    extern __shared__ char smem[];
    const uint32_t sb = smem_u32(smem);
    float* p_s     = reinterpret_cast<float*>(smem + SM_P);
    float* bias_s  = reinterpret_cast<float*>(smem + SM_BIAS);
    float* scale_s = reinterpret_cast<float*>(smem + SM_SCALE);

    const int i = blockIdx.x;
    const int b = blockIdx.y;
    const int t = threadIdx.x;
    const int wid  = t >> 5;
    const int lane = t & 31;

    // --- cp.async A tile 0 first (no smem dependencies) ---
    #pragma unroll 4
    for (int idx = t; idx < 2048; idx += 128) {
        int row = idx >> 4;
        int c16 = idx & 15;
        uint32_t dst = sb + SM_A + row * LDA + c16 * 16;
        const __half* src = g_ch + ((size_t)b * NC_ + row) * D_ + c16 * 8;
        asm volatile("cp.async.cg.shared.global [%0], [%1], 16;"
                     :: "r"(dst), "l"(src) : "memory");
    }

    // --- small loads: p row, bias, mask scales (all 512 j) ---
    if (t < 32) {
        float4 v = reinterpret_cast<const float4*>(g_pn + ((size_t)b * NP_ + i) * D_)[t];
        p_s[t * 4 + 0] = v.x; p_s[t * 4 + 1] = v.y;
        p_s[t * 4 + 2] = v.z; p_s[t * 4 + 3] = v.w;
    } else if (t < 64) {
        reinterpret_cast<float4*>(bias_s)[t - 32] =
            reinterpret_cast<const float4*>(bias)[t - 32];
    }
    {
        const bool pm = p_mask[b * NP_ + i] != 0;
        const int4 cm = reinterpret_cast<const int4*>(c_mask + b * NC_)[t];
        float4 sc;
        sc.x = (pm && cm.x) ? 1.0f : 0.0f;
        sc.y = (pm && cm.y) ? 1.0f : 0.0f;
        sc.z = (pm && cm.z) ? 1.0f : 0.0f;
        sc.w = (pm && cm.w) ? 1.0f : 0.0f;
        reinterpret_cast<float4*>(scale_s)[t] = sc;
    }
    __syncthreads();   // p_s visible

    // --- Build B = W o p_i, fp16 (once per CTA) ---
    #pragma unroll 4
    for (int u = t; u < 4096; u += 128) {
        int row = u >> 5;          // h
        int q   = u & 31;          // float4 index
        float4 w4 = reinterpret_cast<const float4*>(W + (size_t)row * D_)[q];
        int k = q * 4;
        __half2 h01 = __floats2half2_rn(w4.x * p_s[k + 0], w4.y * p_s[k + 1]);
        __half2 h23 = __floats2half2_rn(w4.z * p_s[k + 2], w4.w * p_s[k + 3]);
        uint2 hw;
        hw.x = *reinterpret_cast<uint32_t*>(&h01);
        hw.y = *reinterpret_cast<uint32_t*>(&h23);
        *reinterpret_cast<uint2*>(smem + SM_BHI + row * LDA + k * 2) = hw;
    }
    asm volatile("cp.async.wait_all;" ::: "memory");
    __syncthreads();

    const int wm = wid & 1;      // m: 64 j-rows each
    const int wn = wid >> 1;     // n: 64 h-cols each

    const uint32_t a_lane = (uint32_t)((wm * 64 + (lane & 15)) * LDA + (lane >> 4) * 16);
    const uint32_t b_lane = (uint32_t)((wn * 64 + (lane & 15)) * LDA + (lane >> 4) * 16);
    const uint32_t abase  = sb + SM_A   + a_lane;
    const uint32_t bhbase = sb + SM_BHI + b_lane;

    const int g   = lane >> 2;
    const int tig = lane & 3;

    #pragma unroll 1
    for (int jt = 0; jt < 4; jt++) {
        const int j0 = jt * 128;

        // --- Mainloop: warp tile 64x64, single-pass fp16 ---
        float acc[4][8][4];
        #pragma unroll
        for (int mf = 0; mf < 4; mf++)
            #pragma unroll
            for (int nf = 0; nf < 8; nf++)
                #pragma unroll
                for (int r = 0; r < 4; r++) acc[mf][nf][r] = 0.0f;

        #pragma unroll
        for (int ks = 0; ks < 8; ks++) {
            uint32_t ar[4][4];
            uint32_t bh[4][4];
            #pragma unroll
            for (int mf = 0; mf < 4; mf++) {
                uint32_t addr = abase + mf * (16 * LDA) + ks * 32;
                asm volatile("ldmatrix.sync.aligned.m8n8.x4.shared.b16 {%0,%1,%2,%3}, [%4];"
                             : "=r"(ar[mf][0]), "=r"(ar[mf][1]),
                               "=r"(ar[mf][2]), "=r"(ar[mf][3]) : "r"(addr));
            }
            #pragma unroll
            for (int np = 0; np < 4; np++) {
                uint32_t addr = bhbase + np * (16 * LDA) + ks * 32;
                asm volatile("ldmatrix.sync.aligned.m8n8.x4.shared.b16 {%0,%1,%2,%3}, [%4];"
                             : "=r"(bh[np][0]), "=r"(bh[np][1]),
                               "=r"(bh[np][2]), "=r"(bh[np][3]) : "r"(addr));
            }
            #pragma unroll
            for (int mf = 0; mf < 4; mf++) {
                #pragma unroll
                for (int np = 0; np < 4; np++) {
                    #pragma unroll
                    for (int sel = 0; sel < 2; sel++) {
                        const int nf = np * 2 + sel;
                        asm volatile(
                            "mma.sync.aligned.m16n8k16.row.col.f32.f16.f16.f32 "
                            "{%0,%1,%2,%3}, {%4,%5,%6,%7}, {%8,%9}, {%0,%1,%2,%3};"
                            : "+f"(acc[mf][nf][0]), "+f"(acc[mf][nf][1]),
                              "+f"(acc[mf][nf][2]), "+f"(acc[mf][nf][3])
                            : "r"(ar[mf][0]), "r"(ar[mf][1]), "r"(ar[mf][2]), "r"(ar[mf][3]),
                              "r"(bh[np][sel]), "r"(bh[np][2 + sel]));
                    }
                }
            }
        }
        __syncthreads();   // all warps done reading A tile jt

        // --- Prefetch A tile jt+1 (overlaps epilogue) ---
        if (jt < 3) {
            const int j0n = (jt + 1) * 128;
            #pragma unroll 4
            for (int idx = t; idx < 2048; idx += 128) {
                int row = idx >> 4;
                int c16 = idx & 15;
                uint32_t dst = sb + SM_A + row * LDA + c16 * 16;
                const __half* src = g_ch + ((size_t)b * NC_ + j0n + row) * D_ + c16 * 8;
                asm volatile("cp.async.cg.shared.global [%0], [%1], 16;"
                             :: "r"(dst), "l"(src) : "memory");
            }
        }

        // --- Epilogue: bias + mask, fp32 stores ---
        #pragma unroll
        for (int mf = 0; mf < 4; mf++) {
            const int jl = j0 + wm * 64 + mf * 16 + g;
            const float s0 = scale_s[jl];
            const float s1 = scale_s[jl + 8];
            float* r0p = out + (((size_t)b * NP_ + i) * NC_ + jl) * P_ + wn * 64 + tig * 2;
            float* r1p = r0p + (size_t)8 * P_;
            #pragma unroll
            for (int nf = 0; nf < 8; nf++) {
                const int h = wn * 64 + nf * 8 + tig * 2;
                float2 v0, v1;
                v0.x = (acc[mf][nf][0] + bias_s[h])     * s0;
                v0.y = (acc[mf][nf][1] + bias_s[h + 1]) * s0;
                v1.x = (acc[mf][nf][2] + bias_s[h])     * s1;
                v1.y = (acc[mf][nf][3] + bias_s[h + 1]) * s1;
                *reinterpret_cast<float2*>(r0p + nf * 8) = v0;
                *reinterpret_cast<float2*>(r1p + nf * 8) = v1;
            }
        }

        asm volatile("cp.async.wait_all;" ::: "memory");
        __syncthreads();
    }
}

// ---------------------------------------------------------------------------
// inter_mask second-output kernels
// ---------------------------------------------------------------------------
__global__ void mask_float_kernel(const int* __restrict__ p_mask,
                                  const int* __restrict__ c_mask,
                                  float* __restrict__ out, long n) {
    long idx = (long)blockIdx.x * blockDim.x + threadIdx.x;
    if (idx >= n) return;
    int j  = (int)(idx & (NC_ - 1));
    long bi = idx >> 9;
    int i  = (int)(bi & (NP_ - 1));
    int b  = (int)(bi >> 9);
    out[idx] = (p_mask[b * NP_ + i] && c_mask[b * NC_ + j]) ? 1.0f : 0.0f;
}
__global__ void mask_byte_kernel(const int* __restrict__ p_mask,
                                 const int* __restrict__ c_mask,
                                 unsigned char* __restrict__ out, long n) {
    long idx = (long)blockIdx.x * blockDim.x + threadIdx.x;
    if (idx >= n) return;
    int j  = (int)(idx & (NC_ - 1));
    long bi = idx >> 9;
    int i  = (int)(bi & (NP_ - 1));
    int b  = (int)(bi >> 9);
    out[idx] = (p_mask[b * NP_ + i] && c_mask[b * NC_ + j]) ? 1 : 0;
}

// ---------------------------------------------------------------------------
extern "C" void kernel_launch(void* const* d_in, const int* in_sizes, int n_in,
                              void* d_out, int out_size) {
    const float* p_embed = (const float*)d_in[0];
    const float* c_embed = (const float*)d_in[1];
    const int*   p_mask  = (const int*)d_in[2];
    const int*   c_mask  = (const int*)d_in[3];
    const float* ln_p_w  = (const float*)d_in[4];
    const float* ln_p_b  = (const float*)d_in[5];
    const float* ln_c_w  = (const float*)d_in[6];
    const float* ln_c_b  = (const float*)d_in[7];
    const float* W_out   = (const float*)d_in[8];
    const float* b_out   = (const float*)d_in[9];
    float* out = (float*)d_out;

    cudaFuncSetAttribute(gemm_mma_kernel,
                         cudaFuncAttributeMaxDynamicSharedMemorySize, SM_TOTAL);

    // LayerNorm (p -> fp32, c -> fp16)
    ln_kernel<<<(B_ * (NP_ + NC_)) / 8, 256>>>(p_embed, c_embed,
                                               ln_p_w, ln_p_b, ln_c_w, ln_c_b);

    // i-persistent single-pass fp16 tensor-core interaction GEMM
    dim3 grid(NP_, B_);
    gemm_mma_kernel<<<grid, 128, SM_TOTAL>>>(p_mask, c_mask, W_out, b_out, out);

    // Second output tail (inter_mask), format-adaptive
    const long inter_elems = (long)B_ * NP_ * NC_ * P_;
    const long mask_elems  = (long)B_ * NP_ * NC_;
    long extra = (long)out_size - inter_elems;
    if (extra == mask_elems / 4) {
        mask_byte_kernel<<<(int)((mask_elems + 255) / 256), 256>>>(
            p_mask, c_mask, (unsigned char*)(out + inter_elems), mask_elems);
    } else if (extra > 0) {
        long n = extra < mask_elems ? extra : mask_elems;
        mask_float_kernel<<<(int)((n + 255) / 256), 256>>>(
            p_mask, c_mask, out + inter_elems, n);
    }
}

// round 8
// speedup vs baseline: 1.4101x; 1.0321x over previous
#include <cuda_runtime.h>
#include <cuda_bf16.h>
#include <cuda_fp16.h>
#include <cstdint>
#include <cstddef>

// Problem dims (fixed)
#define B_   2
#define NP_  512
#define NC_  512
#define D_   128
#define P_   128

// ---------------- device scratch (allocation-free) ----------------
__device__ __align__(16) float  g_pn[(size_t)B_ * NP_ * D_];   // layernormed p, fp32
__device__ __align__(16) __half g_ch[(size_t)B_ * NC_ * D_];   // layernormed c, fp16

__device__ __forceinline__ uint32_t smem_u32(const void* p) {
    uint32_t a;
    asm("{ .reg .u64 t; cvta.to.shared.u64 t, %1; cvt.u32.u64 %0, t; }"
        : "=r"(a) : "l"(p));
    return a;
}

// ---------------- SMEM layout ----------------
#define LDA      272                      // 128 fp16 = 256B + 16B pad
#define SM_P     0                        // 512 B
#define SM_BIAS  512                      // 512 B
#define SM_SCALE 1024                     // 512 floats = 2048 B
#define SM_A     3072
#define SM_BHI   (SM_A + 128 * LDA)
#define SM_TOTAL (SM_BHI + 128 * LDA)     // 72704 bytes -> 2 CTAs/SM

// ---------------------------------------------------------------------------
// LayerNorm: one warp per row. p rows -> fp32; c rows -> fp16.
// ---------------------------------------------------------------------------
__global__ void ln_kernel(const float* __restrict__ p_in,
                          const float* __restrict__ c_in,
                          const float* __restrict__ pw, const float* __restrict__ pb,
                          const float* __restrict__ cw, const float* __restrict__ cb) {
    int gwarp = (blockIdx.x * blockDim.x + threadIdx.x) >> 5;
    int lane  = threadIdx.x & 31;
    if (gwarp >= B_ * (NP_ + NC_)) return;

    bool is_p = gwarp < B_ * NP_;
    int row = is_p ? gwarp : gwarp - B_ * NP_;
    const float* src = is_p ? p_in : c_in;
    const float* w   = is_p ? pw : cw;
    const float* bb  = is_p ? pb : cb;

    float4 v = reinterpret_cast<const float4*>(src + (size_t)row * D_)[lane];

    float s = v.x + v.y + v.z + v.w;
    #pragma unroll
    for (int o = 16; o > 0; o >>= 1) s += __shfl_xor_sync(0xFFFFFFFFu, s, o);
    float mu = s * (1.0f / D_);

    float dx = v.x - mu, dy = v.y - mu, dz = v.z - mu, dw = v.w - mu;
    float q = dx * dx + dy * dy + dz * dz + dw * dw;
    #pragma unroll
    for (int o = 16; o > 0; o >>= 1) q += __shfl_xor_sync(0xFFFFFFFFu, q, o);
    float inv = rsqrtf(q * (1.0f / D_) + 1e-5f);

    float4 wv = reinterpret_cast<const float4*>(w)[lane];
    float4 bv = reinterpret_cast<const float4*>(bb)[lane];
    float o0 = dx * inv * wv.x + bv.x;
    float o1 = dy * inv * wv.y + bv.y;
    float o2 = dz * inv * wv.z + bv.z;
    float o3 = dw * inv * wv.w + bv.w;

    if (is_p) {
        float4 o4 = {o0, o1, o2, o3};
        reinterpret_cast<float4*>(g_pn + (size_t)row * D_)[lane] = o4;
    } else {
        __half2 h01 = __floats2half2_rn(o0, o1);
        __half2 h23 = __floats2half2_rn(o2, o3);
        uint2 hw;
        hw.x = *reinterpret_cast<uint32_t*>(&h01);
        hw.y = *reinterpret_cast<uint32_t*>(&h23);
        reinterpret_cast<uint2*>(g_ch + (size_t)row * D_)[lane] = hw;
    }
}

// ---------------------------------------------------------------------------
// Single-pass fp16 warp-MMA interaction kernel, i-persistent, phase-staggered.
// Grid (i=512, b=2), 128 threads = 4 warps in 2(m) x 2(n), warp tile 64x64.
// Odd-i CTAs walk j-tiles in order (2,3,0,1) so co-resident CTAs on one SM
// run opposite phases (one stores while the other runs tensor mainloop).
// Output stores use .cs streaming hint (write-once 256 MB stream).
// ---------------------------------------------------------------------------
__global__ __launch_bounds__(128, 2)
void gemm_mma_kernel(const int* __restrict__ p_mask,
                     const int* __restrict__ c_mask,
                     const float* __restrict__ W,
                     const float* __restrict__ bias,
                     float* __restrict__ out) {
    extern __shared__ char smem[];
    const uint32_t sb = smem_u32(smem);
    float* p_s     = reinterpret_cast<float*>(smem + SM_P);
    float* bias_s  = reinterpret_cast<float*>(smem + SM_BIAS);
    float* scale_s = reinterpret_cast<float*>(smem + SM_SCALE);

    const int i = blockIdx.x;
    const int b = blockIdx.y;
    const int t = threadIdx.x;
    const int wid  = t >> 5;
    const int lane = t & 31;
    const int phase = (i & 1) * 2;       // 0 or 2: stagger j-tile order per CTA

    // --- cp.async A tile for first j-tile (no smem dependencies) ---
    {
        const int j0f = phase * 128;
        #pragma unroll 4
        for (int idx = t; idx < 2048; idx += 128) {
            int row = idx >> 4;
            int c16 = idx & 15;
            uint32_t dst = sb + SM_A + row * LDA + c16 * 16;
            const __half* src = g_ch + ((size_t)b * NC_ + j0f + row) * D_ + c16 * 8;
            asm volatile("cp.async.cg.shared.global [%0], [%1], 16;"
                         :: "r"(dst), "l"(src) : "memory");
        }
    }

    // --- small loads: p row, bias, mask scales (all 512 j) ---
    if (t < 32) {
        float4 v = reinterpret_cast<const float4*>(g_pn + ((size_t)b * NP_ + i) * D_)[t];
        p_s[t * 4 + 0] = v.x; p_s[t * 4 + 1] = v.y;
        p_s[t * 4 + 2] = v.z; p_s[t * 4 + 3] = v.w;
    } else if (t < 64) {
        reinterpret_cast<float4*>(bias_s)[t - 32] =
            reinterpret_cast<const float4*>(bias)[t - 32];
    }
    {
        const bool pm = p_mask[b * NP_ + i] != 0;
        const int4 cm = reinterpret_cast<const int4*>(c_mask + b * NC_)[t];
        float4 sc;
        sc.x = (pm && cm.x) ? 1.0f : 0.0f;
        sc.y = (pm && cm.y) ? 1.0f : 0.0f;
        sc.z = (pm && cm.z) ? 1.0f : 0.0f;
        sc.w = (pm && cm.w) ? 1.0f : 0.0f;
        reinterpret_cast<float4*>(scale_s)[t] = sc;
    }
    __syncthreads();   // p_s visible

    // --- Build B = W o p_i, fp16 (once per CTA) ---
    #pragma unroll 4
    for (int u = t; u < 4096; u += 128) {
        int row = u >> 5;          // h
        int q   = u & 31;          // float4 index
        float4 w4 = reinterpret_cast<const float4*>(W + (size_t)row * D_)[q];
        int k = q * 4;
        __half2 h01 = __floats2half2_rn(w4.x * p_s[k + 0], w4.y * p_s[k + 1]);
        __half2 h23 = __floats2half2_rn(w4.z * p_s[k + 2], w4.w * p_s[k + 3]);
        uint2 hw;
        hw.x = *reinterpret_cast<uint32_t*>(&h01);
        hw.y = *reinterpret_cast<uint32_t*>(&h23);
        *reinterpret_cast<uint2*>(smem + SM_BHI + row * LDA + k * 2) = hw;
    }
    asm volatile("cp.async.wait_all;" ::: "memory");
    __syncthreads();

    const int wm = wid & 1;      // m: 64 j-rows each
    const int wn = wid >> 1;     // n: 64 h-cols each

    const uint32_t a_lane = (uint32_t)((wm * 64 + (lane & 15)) * LDA + (lane >> 4) * 16);
    const uint32_t b_lane = (uint32_t)((wn * 64 + (lane & 15)) * LDA + (lane >> 4) * 16);
    const uint32_t abase  = sb + SM_A   + a_lane;
    const uint32_t bhbase = sb + SM_BHI + b_lane;

    const int g   = lane >> 2;
    const int tig = lane & 3;

    #pragma unroll 1
    for (int jtl = 0; jtl < 4; jtl++) {
        const int jt = (jtl + phase) & 3;
        const int j0 = jt * 128;

        // --- Mainloop: warp tile 64x64, single-pass fp16 ---
        float acc[4][8][4];
        #pragma unroll
        for (int mf = 0; mf < 4; mf++)
            #pragma unroll
            for (int nf = 0; nf < 8; nf++)
                #pragma unroll
                for (int r = 0; r < 4; r++) acc[mf][nf][r] = 0.0f;

        #pragma unroll
        for (int ks = 0; ks < 8; ks++) {
            uint32_t ar[4][4];
            uint32_t bh[4][4];
            #pragma unroll
            for (int mf = 0; mf < 4; mf++) {
                uint32_t addr = abase + mf * (16 * LDA) + ks * 32;
                asm volatile("ldmatrix.sync.aligned.m8n8.x4.shared.b16 {%0,%1,%2,%3}, [%4];"
                             : "=r"(ar[mf][0]), "=r"(ar[mf][1]),
                               "=r"(ar[mf][2]), "=r"(ar[mf][3]) : "r"(addr));
            }
            #pragma unroll
            for (int np = 0; np < 4; np++) {
                uint32_t addr = bhbase + np * (16 * LDA) + ks * 32;
                asm volatile("ldmatrix.sync.aligned.m8n8.x4.shared.b16 {%0,%1,%2,%3}, [%4];"
                             : "=r"(bh[np][0]), "=r"(bh[np][1]),
                               "=r"(bh[np][2]), "=r"(bh[np][3]) : "r"(addr));
            }
            #pragma unroll
            for (int mf = 0; mf < 4; mf++) {
                #pragma unroll
                for (int np = 0; np < 4; np++) {
                    #pragma unroll
                    for (int sel = 0; sel < 2; sel++) {
                        const int nf = np * 2 + sel;
                        asm volatile(
                            "mma.sync.aligned.m16n8k16.row.col.f32.f16.f16.f32 "
                            "{%0,%1,%2,%3}, {%4,%5,%6,%7}, {%8,%9}, {%0,%1,%2,%3};"
                            : "+f"(acc[mf][nf][0]), "+f"(acc[mf][nf][1]),
                              "+f"(acc[mf][nf][2]), "+f"(acc[mf][nf][3])
                            : "r"(ar[mf][0]), "r"(ar[mf][1]), "r"(ar[mf][2]), "r"(ar[mf][3]),
                              "r"(bh[np][sel]), "r"(bh[np][2 + sel]));
                    }
                }
            }
        }
        __syncthreads();   // all warps done reading A tile jt

        // --- Prefetch A tile for next jtl (overlaps epilogue) ---
        if (jtl < 3) {
            const int j0n = (((jtl + 1) + phase) & 3) * 128;
            #pragma unroll 4
            for (int idx = t; idx < 2048; idx += 128) {
                int row = idx >> 4;
                int c16 = idx & 15;
                uint32_t dst = sb + SM_A + row * LDA + c16 * 16;
                const __half* src = g_ch + ((size_t)b * NC_ + j0n + row) * D_ + c16 * 8;
                asm volatile("cp.async.cg.shared.global [%0], [%1], 16;"
                             :: "r"(dst), "l"(src) : "memory");
            }
        }

        // --- Epilogue: bias + mask, streaming fp32 stores ---
        #pragma unroll
        for (int mf = 0; mf < 4; mf++) {
            const int jl = j0 + wm * 64 + mf * 16 + g;
            const float s0 = scale_s[jl];
            const float s1 = scale_s[jl + 8];
            float* r0p = out + (((size_t)b * NP_ + i) * NC_ + jl) * P_ + wn * 64 + tig * 2;
            float* r1p = r0p + (size_t)8 * P_;
            #pragma unroll
            for (int nf = 0; nf < 8; nf++) {
                const int h = wn * 64 + nf * 8 + tig * 2;
                float x0 = (acc[mf][nf][0] + bias_s[h])     * s0;
                float y0 = (acc[mf][nf][1] + bias_s[h + 1]) * s0;
                float x1 = (acc[mf][nf][2] + bias_s[h])     * s1;
                float y1 = (acc[mf][nf][3] + bias_s[h + 1]) * s1;
                asm volatile("st.global.cs.v2.f32 [%0], {%1, %2};"
                             :: "l"(r0p + nf * 8), "f"(x0), "f"(y0) : "memory");
                asm volatile("st.global.cs.v2.f32 [%0], {%1, %2};"
                             :: "l"(r1p + nf * 8), "f"(x1), "f"(y1) : "memory");
            }
        }

        asm volatile("cp.async.wait_all;" ::: "memory");
        __syncthreads();
    }
}

// ---------------------------------------------------------------------------
// inter_mask second-output kernels
// ---------------------------------------------------------------------------
__global__ void mask_float_kernel(const int* __restrict__ p_mask,
                                  const int* __restrict__ c_mask,
                                  float* __restrict__ out, long n) {
    long idx = (long)blockIdx.x * blockDim.x + threadIdx.x;
    if (idx >= n) return;
    int j  = (int)(idx & (NC_ - 1));
    long bi = idx >> 9;
    int i  = (int)(bi & (NP_ - 1));
    int b  = (int)(bi >> 9);
    out[idx] = (p_mask[b * NP_ + i] && c_mask[b * NC_ + j]) ? 1.0f : 0.0f;
}
__global__ void mask_byte_kernel(const int* __restrict__ p_mask,
                                 const int* __restrict__ c_mask,
                                 unsigned char* __restrict__ out, long n) {
    long idx = (long)blockIdx.x * blockDim.x + threadIdx.x;
    if (idx >= n) return;
    int j  = (int)(idx & (NC_ - 1));
    long bi = idx >> 9;
    int i  = (int)(bi & (NP_ - 1));
    int b  = (int)(bi >> 9);
    out[idx] = (p_mask[b * NP_ + i] && c_mask[b * NC_ + j]) ? 1 : 0;
}

// ---------------------------------------------------------------------------
extern "C" void kernel_launch(void* const* d_in, const int* in_sizes, int n_in,
                              void* d_out, int out_size) {
    const float* p_embed = (const float*)d_in[0];
    const float* c_embed = (const float*)d_in[1];
    const int*   p_mask  = (const int*)d_in[2];
    const int*   c_mask  = (const int*)d_in[3];
    const float* ln_p_w  = (const float*)d_in[4];
    const float* ln_p_b  = (const float*)d_in[5];
    const float* ln_c_w  = (const float*)d_in[6];
    const float* ln_c_b  = (const float*)d_in[7];
    const float* W_out   = (const float*)d_in[8];
    const float* b_out   = (const float*)d_in[9];
    float* out = (float*)d_out;

    cudaFuncSetAttribute(gemm_mma_kernel,
                         cudaFuncAttributeMaxDynamicSharedMemorySize, SM_TOTAL);

    // LayerNorm (p -> fp32, c -> fp16)
    ln_kernel<<<(B_ * (NP_ + NC_)) / 8, 256>>>(p_embed, c_embed,
                                               ln_p_w, ln_p_b, ln_c_w, ln_c_b);

    // Phase-staggered single-pass fp16 tensor-core interaction GEMM
    dim3 grid(NP_, B_);
    gemm_mma_kernel<<<grid, 128, SM_TOTAL>>>(p_mask, c_mask, W_out, b_out, out);

    // Second output tail (inter_mask), format-adaptive
    const long inter_elems = (long)B_ * NP_ * NC_ * P_;
    const long mask_elems  = (long)B_ * NP_ * NC_;
    long extra = (long)out_size - inter_elems;
    if (extra == mask_elems / 4) {
        mask_byte_kernel<<<(int)((mask_elems + 255) / 256), 256>>>(
            p_mask, c_mask, (unsigned char*)(out + inter_elems), mask_elems);
    } else if (extra > 0) {
        long n = extra < mask_elems ? extra : mask_elems;
        mask_float_kernel<<<(int)((n + 255) / 256), 256>>>(
            p_mask, c_mask, out + inter_elems, n);
    }
}

// round 9
// speedup vs baseline: 1.4173x; 1.0051x over previous
#include <cuda_runtime.h>
#include <cuda_bf16.h>
#include <cuda_fp16.h>
#include <cstdint>
#include <cstddef>

// Problem dims (fixed)
#define B_   2
#define NP_  512
#define NC_  512
#define D_   128
#define P_   128

// ---------------- device scratch (allocation-free) ----------------
__device__ __align__(16) float  g_pn[(size_t)B_ * NP_ * D_];   // layernormed p, fp32
__device__ __align__(16) __half g_ch[(size_t)B_ * NC_ * D_];   // layernormed c, fp16

__device__ __forceinline__ uint32_t smem_u32(const void* p) {
    uint32_t a;
    asm("{ .reg .u64 t; cvta.to.shared.u64 t, %1; cvt.u32.u64 %0, t; }"
        : "=r"(a) : "l"(p));
    return a;
}

// ---------------- SMEM layout ----------------
#define LDA      272                      // 128 fp16 = 256B + 16B pad
#define SM_P     0                        // 512 B
#define SM_BIAS  512                      // 512 B
#define SM_SCALE 1024                     // 512 floats = 2048 B
#define SM_A0    3072
#define SM_A1    (SM_A0 + 128 * LDA)
#define SM_B     (SM_A1 + 128 * LDA)
#define SM_TOTAL (SM_B  + 128 * LDA)      // 107520 bytes -> 2 CTAs/SM

// ---------------------------------------------------------------------------
// LayerNorm: one warp per row. p rows -> fp32; c rows -> fp16.
// ---------------------------------------------------------------------------
__global__ void ln_kernel(const float* __restrict__ p_in,
                          const float* __restrict__ c_in,
                          const float* __restrict__ pw, const float* __restrict__ pb,
                          const float* __restrict__ cw, const float* __restrict__ cb) {
    int gwarp = (blockIdx.x * blockDim.x + threadIdx.x) >> 5;
    int lane  = threadIdx.x & 31;
    if (gwarp >= B_ * (NP_ + NC_)) return;

    bool is_p = gwarp < B_ * NP_;
    int row = is_p ? gwarp : gwarp - B_ * NP_;
    const float* src = is_p ? p_in : c_in;
    const float* w   = is_p ? pw : cw;
    const float* bb  = is_p ? pb : cb;

    float4 v = reinterpret_cast<const float4*>(src + (size_t)row * D_)[lane];

    float s = v.x + v.y + v.z + v.w;
    #pragma unroll
    for (int o = 16; o > 0; o >>= 1) s += __shfl_xor_sync(0xFFFFFFFFu, s, o);
    float mu = s * (1.0f / D_);

    float dx = v.x - mu, dy = v.y - mu, dz = v.z - mu, dw = v.w - mu;
    float q = dx * dx + dy * dy + dz * dz + dw * dw;
    #pragma unroll
    for (int o = 16; o > 0; o >>= 1) q += __shfl_xor_sync(0xFFFFFFFFu, q, o);
    float inv = rsqrtf(q * (1.0f / D_) + 1e-5f);

    float4 wv = reinterpret_cast<const float4*>(w)[lane];
    float4 bv = reinterpret_cast<const float4*>(bb)[lane];
    float o0 = dx * inv * wv.x + bv.x;
    float o1 = dy * inv * wv.y + bv.y;
    float o2 = dz * inv * wv.z + bv.z;
    float o3 = dw * inv * wv.w + bv.w;

    if (is_p) {
        float4 o4 = {o0, o1, o2, o3};
        reinterpret_cast<float4*>(g_pn + (size_t)row * D_)[lane] = o4;
    } else {
        __half2 h01 = __floats2half2_rn(o0, o1);
        __half2 h23 = __floats2half2_rn(o2, o3);
        uint2 hw;
        hw.x = *reinterpret_cast<uint32_t*>(&h01);
        hw.y = *reinterpret_cast<uint32_t*>(&h23);
        reinterpret_cast<uint2*>(g_ch + (size_t)row * D_)[lane] = hw;
    }
}

// ---------------------------------------------------------------------------
// Single-pass fp16 warp-MMA interaction kernel, i-persistent, phase-staggered,
// A-tile double-buffered (prefetch issued BEFORE the mainloop), inter_mask
// output fused. Grid (i=512, b=2), 128 threads = 4 warps in 2(m) x 2(n).
// mask_mode: 0=none, 1=float per entry, 2=byte per entry.
// ---------------------------------------------------------------------------
__global__ __launch_bounds__(128, 2)
void gemm_mma_kernel(const int* __restrict__ p_mask,
                     const int* __restrict__ c_mask,
                     const float* __restrict__ W,
                     const float* __restrict__ bias,
                     float* __restrict__ out,
                     void* __restrict__ mask_out, int mask_mode) {
    extern __shared__ char smem[];
    const uint32_t sb = smem_u32(smem);
    float* p_s     = reinterpret_cast<float*>(smem + SM_P);
    float* bias_s  = reinterpret_cast<float*>(smem + SM_BIAS);
    float* scale_s = reinterpret_cast<float*>(smem + SM_SCALE);

    const int i = blockIdx.x;
    const int b = blockIdx.y;
    const int t = threadIdx.x;
    const int wid  = t >> 5;
    const int lane = t & 31;
    const int phase = (i & 1) * 2;       // stagger j-tile order per CTA

    const uint32_t abuf[2] = {sb + SM_A0, sb + SM_A1};

    // --- cp.async A tile for first j-tile into buffer 0 ---
    {
        const int j0f = phase * 128;
        #pragma unroll 4
        for (int idx = t; idx < 2048; idx += 128) {
            int row = idx >> 4;
            int c16 = idx & 15;
            uint32_t dst = abuf[0] + row * LDA + c16 * 16;
            const __half* src = g_ch + ((size_t)b * NC_ + j0f + row) * D_ + c16 * 8;
            asm volatile("cp.async.cg.shared.global [%0], [%1], 16;"
                         :: "r"(dst), "l"(src) : "memory");
        }
    }

    // --- small loads: p row, bias, mask scales (all 512 j) ---
    if (t < 32) {
        float4 v = reinterpret_cast<const float4*>(g_pn + ((size_t)b * NP_ + i) * D_)[t];
        p_s[t * 4 + 0] = v.x; p_s[t * 4 + 1] = v.y;
        p_s[t * 4 + 2] = v.z; p_s[t * 4 + 3] = v.w;
    } else if (t < 64) {
        reinterpret_cast<float4*>(bias_s)[t - 32] =
            reinterpret_cast<const float4*>(bias)[t - 32];
    }
    {
        const bool pm = p_mask[b * NP_ + i] != 0;
        const int4 cm = reinterpret_cast<const int4*>(c_mask + b * NC_)[t];
        float4 sc;
        sc.x = (pm && cm.x) ? 1.0f : 0.0f;
        sc.y = (pm && cm.y) ? 1.0f : 0.0f;
        sc.z = (pm && cm.z) ? 1.0f : 0.0f;
        sc.w = (pm && cm.w) ? 1.0f : 0.0f;
        reinterpret_cast<float4*>(scale_s)[t] = sc;
    }
    __syncthreads();   // p_s + scale_s visible

    // --- Fused inter_mask output (CTA owns mask row [b, i, :]) ---
    if (mask_mode == 1) {
        float* mrow = reinterpret_cast<float*>(mask_out) + ((size_t)b * NP_ + i) * NC_;
        reinterpret_cast<float4*>(mrow)[t] = reinterpret_cast<float4*>(scale_s)[t];
    } else if (mask_mode == 2) {
        unsigned char* mrow = reinterpret_cast<unsigned char*>(mask_out)
                            + ((size_t)b * NP_ + i) * NC_;
        float4 sc = reinterpret_cast<float4*>(scale_s)[t];
        uchar4 u;
        u.x = (unsigned char)(sc.x != 0.0f);
        u.y = (unsigned char)(sc.y != 0.0f);
        u.z = (unsigned char)(sc.z != 0.0f);
        u.w = (unsigned char)(sc.w != 0.0f);
        reinterpret_cast<uchar4*>(mrow)[t] = u;
    }

    // --- Build B = W o p_i, fp16 (once per CTA) ---
    #pragma unroll 4
    for (int u = t; u < 4096; u += 128) {
        int row = u >> 5;          // h
        int q   = u & 31;          // float4 index
        float4 w4 = reinterpret_cast<const float4*>(W + (size_t)row * D_)[q];
        int k = q * 4;
        __half2 h01 = __floats2half2_rn(w4.x * p_s[k + 0], w4.y * p_s[k + 1]);
        __half2 h23 = __floats2half2_rn(w4.z * p_s[k + 2], w4.w * p_s[k + 3]);
        uint2 hw;
        hw.x = *reinterpret_cast<uint32_t*>(&h01);
        hw.y = *reinterpret_cast<uint32_t*>(&h23);
        *reinterpret_cast<uint2*>(smem + SM_B + row * LDA + k * 2) = hw;
    }
    asm volatile("cp.async.wait_all;" ::: "memory");
    __syncthreads();

    const int wm = wid & 1;      // m: 64 j-rows each
    const int wn = wid >> 1;     // n: 64 h-cols each

    const uint32_t a_lane = (uint32_t)((wm * 64 + (lane & 15)) * LDA + (lane >> 4) * 16);
    const uint32_t b_lane = (uint32_t)((wn * 64 + (lane & 15)) * LDA + (lane >> 4) * 16);
    const uint32_t bhbase = sb + SM_B + b_lane;

    const int g   = lane >> 2;
    const int tig = lane & 3;

    #pragma unroll 1
    for (int jtl = 0; jtl < 4; jtl++) {
        const int jt = (jtl + phase) & 3;
        const int j0 = jt * 128;
        const int cur = jtl & 1;

        // --- Prefetch next A tile into the other buffer BEFORE mainloop ---
        if (jtl < 3) {
            const int j0n = (((jtl + 1) + phase) & 3) * 128;
            #pragma unroll 4
            for (int idx = t; idx < 2048; idx += 128) {
                int row = idx >> 4;
                int c16 = idx & 15;
                uint32_t dst = abuf[cur ^ 1] + row * LDA + c16 * 16;
                const __half* src = g_ch + ((size_t)b * NC_ + j0n + row) * D_ + c16 * 8;
                asm volatile("cp.async.cg.shared.global [%0], [%1], 16;"
                             :: "r"(dst), "l"(src) : "memory");
            }
        }

        // --- Mainloop: warp tile 64x64, single-pass fp16 ---
        const uint32_t abase = abuf[cur] + a_lane;
        float acc[4][8][4];
        #pragma unroll
        for (int mf = 0; mf < 4; mf++)
            #pragma unroll
            for (int nf = 0; nf < 8; nf++)
                #pragma unroll
                for (int r = 0; r < 4; r++) acc[mf][nf][r] = 0.0f;

        #pragma unroll
        for (int ks = 0; ks < 8; ks++) {
            uint32_t ar[4][4];
            uint32_t bh[4][4];
            #pragma unroll
            for (int mf = 0; mf < 4; mf++) {
                uint32_t addr = abase + mf * (16 * LDA) + ks * 32;
                asm volatile("ldmatrix.sync.aligned.m8n8.x4.shared.b16 {%0,%1,%2,%3}, [%4];"
                             : "=r"(ar[mf][0]), "=r"(ar[mf][1]),
                               "=r"(ar[mf][2]), "=r"(ar[mf][3]) : "r"(addr));
            }
            #pragma unroll
            for (int np = 0; np < 4; np++) {
                uint32_t addr = bhbase + np * (16 * LDA) + ks * 32;
                asm volatile("ldmatrix.sync.aligned.m8n8.x4.shared.b16 {%0,%1,%2,%3}, [%4];"
                             : "=r"(bh[np][0]), "=r"(bh[np][1]),
                               "=r"(bh[np][2]), "=r"(bh[np][3]) : "r"(addr));
            }
            #pragma unroll
            for (int mf = 0; mf < 4; mf++) {
                #pragma unroll
                for (int np = 0; np < 4; np++) {
                    #pragma unroll
                    for (int sel = 0; sel < 2; sel++) {
                        const int nf = np * 2 + sel;
                        asm volatile(
                            "mma.sync.aligned.m16n8k16.row.col.f32.f16.f16.f32 "
                            "{%0,%1,%2,%3}, {%4,%5,%6,%7}, {%8,%9}, {%0,%1,%2,%3};"
                            : "+f"(acc[mf][nf][0]), "+f"(acc[mf][nf][1]),
                              "+f"(acc[mf][nf][2]), "+f"(acc[mf][nf][3])
                            : "r"(ar[mf][0]), "r"(ar[mf][1]), "r"(ar[mf][2]), "r"(ar[mf][3]),
                              "r"(bh[np][sel]), "r"(bh[np][2 + sel]));
                    }
                }
            }
        }

        // --- Epilogue: bias + mask, streaming fp32 stores ---
        #pragma unroll
        for (int mf = 0; mf < 4; mf++) {
            const int jl = j0 + wm * 64 + mf * 16 + g;
            const float s0 = scale_s[jl];
            const float s1 = scale_s[jl + 8];
            float* r0p = out + (((size_t)b * NP_ + i) * NC_ + jl) * P_ + wn * 64 + tig * 2;
            float* r1p = r0p + (size_t)8 * P_;
            #pragma unroll
            for (int nf = 0; nf < 8; nf++) {
                const int h = wn * 64 + nf * 8 + tig * 2;
                float x0 = (acc[mf][nf][0] + bias_s[h])     * s0;
                float y0 = (acc[mf][nf][1] + bias_s[h + 1]) * s0;
                float x1 = (acc[mf][nf][2] + bias_s[h])     * s1;
                float y1 = (acc[mf][nf][3] + bias_s[h + 1]) * s1;
                asm volatile("st.global.cs.v2.f32 [%0], {%1, %2};"
                             :: "l"(r0p + nf * 8), "f"(x0), "f"(y0) : "memory");
                asm volatile("st.global.cs.v2.f32 [%0], {%1, %2};"
                             :: "l"(r1p + nf * 8), "f"(x1), "f"(y1) : "memory");
            }
        }

        // --- Close the tile: prefetch must be complete, all warps past mainloop ---
        if (jtl < 3) {
            asm volatile("cp.async.wait_all;" ::: "memory");
            __syncthreads();
        }
    }
}

// ---------------------------------------------------------------------------
// Fallback inter_mask kernel (only for unexpected tail sizes)
// ---------------------------------------------------------------------------
__global__ void mask_float_kernel(const int* __restrict__ p_mask,
                                  const int* __restrict__ c_mask,
                                  float* __restrict__ out, long n) {
    long idx = (long)blockIdx.x * blockDim.x + threadIdx.x;
    if (idx >= n) return;
    int j  = (int)(idx & (NC_ - 1));
    long bi = idx >> 9;
    int i  = (int)(bi & (NP_ - 1));
    int b  = (int)(bi >> 9);
    out[idx] = (p_mask[b * NP_ + i] && c_mask[b * NC_ + j]) ? 1.0f : 0.0f;
}

// ---------------------------------------------------------------------------
extern "C" void kernel_launch(void* const* d_in, const int* in_sizes, int n_in,
                              void* d_out, int out_size) {
    const float* p_embed = (const float*)d_in[0];
    const float* c_embed = (const float*)d_in[1];
    const int*   p_mask  = (const int*)d_in[2];
    const int*   c_mask  = (const int*)d_in[3];
    const float* ln_p_w  = (const float*)d_in[4];
    const float* ln_p_b  = (const float*)d_in[5];
    const float* ln_c_w  = (const float*)d_in[6];
    const float* ln_c_b  = (const float*)d_in[7];
    const float* W_out   = (const float*)d_in[8];
    const float* b_out   = (const float*)d_in[9];
    float* out = (float*)d_out;

    cudaFuncSetAttribute(gemm_mma_kernel,
                         cudaFuncAttributeMaxDynamicSharedMemorySize, SM_TOTAL);

    // LayerNorm (p -> fp32, c -> fp16)
    ln_kernel<<<(B_ * (NP_ + NC_)) / 8, 256>>>(p_embed, c_embed,
                                               ln_p_w, ln_p_b, ln_c_w, ln_c_b);

    // Decide inter_mask tail format
    const long inter_elems = (long)B_ * NP_ * NC_ * P_;
    const long mask_elems  = (long)B_ * NP_ * NC_;
    long extra = (long)out_size - inter_elems;
    void* mask_out = nullptr;
    int mask_mode = 0;
    if (extra >= mask_elems) {
        mask_out = (void*)(out + inter_elems); mask_mode = 1;      // float per entry
    } else if (extra == mask_elems / 4) {
        mask_out = (void*)(out + inter_elems); mask_mode = 2;      // byte per entry
    }

    // Phase-staggered, double-buffered fp16 tensor-core interaction GEMM
    dim3 grid(NP_, B_);
    gemm_mma_kernel<<<grid, 128, SM_TOTAL>>>(p_mask, c_mask, W_out, b_out, out,
                                             mask_out, mask_mode);

    // Fallback for odd partial tails only
    if (mask_mode == 0 && extra > 0) {
        long n = extra < mask_elems ? extra : mask_elems;
        mask_float_kernel<<<(int)((n + 255) / 256), 256>>>(
            p_mask, c_mask, out + inter_elems, n);
    }
}

// round 10
// speedup vs baseline: 1.4702x; 1.0373x over previous
#include <cuda_runtime.h>
#include <cuda_bf16.h>
#include <cuda_fp16.h>
#include <cstdint>
#include <cstddef>

// Problem dims (fixed)
#define B_   2
#define NP_  512
#define NC_  512
#define D_   128
#define P_   128

// ---------------- device scratch (allocation-free) ----------------
__device__ __align__(16) float  g_pn[(size_t)B_ * NP_ * D_];   // layernormed p, fp32
__device__ __align__(16) __half g_ch[(size_t)B_ * NC_ * D_];   // layernormed c, fp16

__device__ __forceinline__ uint32_t smem_u32(const void* p) {
    uint32_t a;
    asm("{ .reg .u64 t; cvta.to.shared.u64 t, %1; cvt.u32.u64 %0, t; }"
        : "=r"(a) : "l"(p));
    return a;
}

// ---------------- SMEM layout ----------------
#define LDA      272                      // 128 fp16 = 256B + 16B pad
#define SM_P     0                        // 512 B
#define SM_BIAS  512                      // 512 B
#define SM_SCALE 1024                     // 512 floats = 2048 B
#define SM_A     3072
#define SM_B     (SM_A + 128 * LDA)
#define SM_TOTAL (SM_B + 128 * LDA)       // 72704 bytes -> 3 CTAs/SM (smem)

// ---------------------------------------------------------------------------
// LayerNorm: one warp per row. p rows -> fp32; c rows -> fp16.
// ---------------------------------------------------------------------------
__global__ void ln_kernel(const float* __restrict__ p_in,
                          const float* __restrict__ c_in,
                          const float* __restrict__ pw, const float* __restrict__ pb,
                          const float* __restrict__ cw, const float* __restrict__ cb) {
    int gwarp = (blockIdx.x * blockDim.x + threadIdx.x) >> 5;
    int lane  = threadIdx.x & 31;
    if (gwarp >= B_ * (NP_ + NC_)) return;

    bool is_p = gwarp < B_ * NP_;
    int row = is_p ? gwarp : gwarp - B_ * NP_;
    const float* src = is_p ? p_in : c_in;
    const float* w   = is_p ? pw : cw;
    const float* bb  = is_p ? pb : cb;

    float4 v = reinterpret_cast<const float4*>(src + (size_t)row * D_)[lane];

    float s = v.x + v.y + v.z + v.w;
    #pragma unroll
    for (int o = 16; o > 0; o >>= 1) s += __shfl_xor_sync(0xFFFFFFFFu, s, o);
    float mu = s * (1.0f / D_);

    float dx = v.x - mu, dy = v.y - mu, dz = v.z - mu, dw = v.w - mu;
    float q = dx * dx + dy * dy + dz * dz + dw * dw;
    #pragma unroll
    for (int o = 16; o > 0; o >>= 1) q += __shfl_xor_sync(0xFFFFFFFFu, q, o);
    float inv = rsqrtf(q * (1.0f / D_) + 1e-5f);

    float4 wv = reinterpret_cast<const float4*>(w)[lane];
    float4 bv = reinterpret_cast<const float4*>(bb)[lane];
    float o0 = dx * inv * wv.x + bv.x;
    float o1 = dy * inv * wv.y + bv.y;
    float o2 = dz * inv * wv.z + bv.z;
    float o3 = dw * inv * wv.w + bv.w;

    if (is_p) {
        float4 o4 = {o0, o1, o2, o3};
        reinterpret_cast<float4*>(g_pn + (size_t)row * D_)[lane] = o4;
    } else {
        __half2 h01 = __floats2half2_rn(o0, o1);
        __half2 h23 = __floats2half2_rn(o2, o3);
        uint2 hw;
        hw.x = *reinterpret_cast<uint32_t*>(&h01);
        hw.y = *reinterpret_cast<uint32_t*>(&h23);
        reinterpret_cast<uint2*>(g_ch + (size_t)row * D_)[lane] = hw;
    }
}

// ---------------------------------------------------------------------------
// Single-pass fp16 warp-MMA interaction kernel, i-persistent, phase-staggered,
// fused inter_mask. Grid (i=512, b=2), 128 threads = 4 warps in 2(m) x 2(n),
// warp tile 64x64. 3 CTAs/SM target (regs <= 170 via launch_bounds).
// mask_mode: 0=none, 1=float per entry, 2=byte per entry.
// ---------------------------------------------------------------------------
__global__ __launch_bounds__(128, 3)
void gemm_mma_kernel(const int* __restrict__ p_mask,
                     const int* __restrict__ c_mask,
                     const float* __restrict__ W,
                     const float* __restrict__ bias,
                     float* __restrict__ out,
                     void* __restrict__ mask_out, int mask_mode) {
    extern __shared__ char smem[];
    const uint32_t sb = smem_u32(smem);
    float* p_s     = reinterpret_cast<float*>(smem + SM_P);
    float* bias_s  = reinterpret_cast<float*>(smem + SM_BIAS);
    float* scale_s = reinterpret_cast<float*>(smem + SM_SCALE);

    const int i = blockIdx.x;
    const int b = blockIdx.y;
    const int t = threadIdx.x;
    const int wid  = t >> 5;
    const int lane = t & 31;
    const int phase = (i & 1) * 2;       // stagger j-tile order per CTA

    // --- cp.async A tile for first j-tile ---
    {
        const int j0f = phase * 128;
        #pragma unroll 4
        for (int idx = t; idx < 2048; idx += 128) {
            int row = idx >> 4;
            int c16 = idx & 15;
            uint32_t dst = sb + SM_A + row * LDA + c16 * 16;
            const __half* src = g_ch + ((size_t)b * NC_ + j0f + row) * D_ + c16 * 8;
            asm volatile("cp.async.cg.shared.global [%0], [%1], 16;"
                         :: "r"(dst), "l"(src) : "memory");
        }
    }

    // --- small loads: p row, bias, mask scales (all 512 j) ---
    if (t < 32) {
        float4 v = reinterpret_cast<const float4*>(g_pn + ((size_t)b * NP_ + i) * D_)[t];
        p_s[t * 4 + 0] = v.x; p_s[t * 4 + 1] = v.y;
        p_s[t * 4 + 2] = v.z; p_s[t * 4 + 3] = v.w;
    } else if (t < 64) {
        reinterpret_cast<float4*>(bias_s)[t - 32] =
            reinterpret_cast<const float4*>(bias)[t - 32];
    }
    {
        const bool pm = p_mask[b * NP_ + i] != 0;
        const int4 cm = reinterpret_cast<const int4*>(c_mask + b * NC_)[t];
        float4 sc;
        sc.x = (pm && cm.x) ? 1.0f : 0.0f;
        sc.y = (pm && cm.y) ? 1.0f : 0.0f;
        sc.z = (pm && cm.z) ? 1.0f : 0.0f;
        sc.w = (pm && cm.w) ? 1.0f : 0.0f;
        reinterpret_cast<float4*>(scale_s)[t] = sc;
    }
    __syncthreads();   // p_s + scale_s visible

    // --- Fused inter_mask output (CTA owns mask row [b, i, :]) ---
    if (mask_mode == 1) {
        float* mrow = reinterpret_cast<float*>(mask_out) + ((size_t)b * NP_ + i) * NC_;
        reinterpret_cast<float4*>(mrow)[t] = reinterpret_cast<float4*>(scale_s)[t];
    } else if (mask_mode == 2) {
        unsigned char* mrow = reinterpret_cast<unsigned char*>(mask_out)
                            + ((size_t)b * NP_ + i) * NC_;
        float4 sc = reinterpret_cast<float4*>(scale_s)[t];
        uchar4 u;
        u.x = (unsigned char)(sc.x != 0.0f);
        u.y = (unsigned char)(sc.y != 0.0f);
        u.z = (unsigned char)(sc.z != 0.0f);
        u.w = (unsigned char)(sc.w != 0.0f);
        reinterpret_cast<uchar4*>(mrow)[t] = u;
    }

    // --- Build B = W o p_i, fp16 (once per CTA) ---
    #pragma unroll 4
    for (int u = t; u < 4096; u += 128) {
        int row = u >> 5;          // h
        int q   = u & 31;          // float4 index
        float4 w4 = reinterpret_cast<const float4*>(W + (size_t)row * D_)[q];
        int k = q * 4;
        __half2 h01 = __floats2half2_rn(w4.x * p_s[k + 0], w4.y * p_s[k + 1]);
        __half2 h23 = __floats2half2_rn(w4.z * p_s[k + 2], w4.w * p_s[k + 3]);
        uint2 hw;
        hw.x = *reinterpret_cast<uint32_t*>(&h01);
        hw.y = *reinterpret_cast<uint32_t*>(&h23);
        *reinterpret_cast<uint2*>(smem + SM_B + row * LDA + k * 2) = hw;
    }
    asm volatile("cp.async.wait_all;" ::: "memory");
    __syncthreads();

    const int wm = wid & 1;      // m: 64 j-rows each
    const int wn = wid >> 1;     // n: 64 h-cols each

    const uint32_t a_lane = (uint32_t)((wm * 64 + (lane & 15)) * LDA + (lane >> 4) * 16);
    const uint32_t b_lane = (uint32_t)((wn * 64 + (lane & 15)) * LDA + (lane >> 4) * 16);
    const uint32_t abase  = sb + SM_A + a_lane;
    const uint32_t bhbase = sb + SM_B + b_lane;

    const int g   = lane >> 2;
    const int tig = lane & 3;

    #pragma unroll 1
    for (int jtl = 0; jtl < 4; jtl++) {
        const int jt = (jtl + phase) & 3;
        const int j0 = jt * 128;

        // --- Mainloop: warp tile 64x64, low register pressure ---
        float acc[4][8][4];
        #pragma unroll
        for (int mf = 0; mf < 4; mf++)
            #pragma unroll
            for (int nf = 0; nf < 8; nf++)
                #pragma unroll
                for (int r = 0; r < 4; r++) acc[mf][nf][r] = 0.0f;

        #pragma unroll
        for (int ks = 0; ks < 8; ks++) {
            // Load all B fragments for this ks (16 regs live)
            uint32_t bh[4][4];
            #pragma unroll
            for (int np = 0; np < 4; np++) {
                uint32_t addr = bhbase + np * (16 * LDA) + ks * 32;
                asm volatile("ldmatrix.sync.aligned.m8n8.x4.shared.b16 {%0,%1,%2,%3}, [%4];"
                             : "=r"(bh[np][0]), "=r"(bh[np][1]),
                               "=r"(bh[np][2]), "=r"(bh[np][3]) : "r"(addr));
            }
            // Stream A one mf at a time (only 4 A regs live)
            #pragma unroll
            for (int mf = 0; mf < 4; mf++) {
                uint32_t ar[4];
                uint32_t addr = abase + mf * (16 * LDA) + ks * 32;
                asm volatile("ldmatrix.sync.aligned.m8n8.x4.shared.b16 {%0,%1,%2,%3}, [%4];"
                             : "=r"(ar[0]), "=r"(ar[1]), "=r"(ar[2]), "=r"(ar[3])
                             : "r"(addr));
                #pragma unroll
                for (int np = 0; np < 4; np++) {
                    #pragma unroll
                    for (int sel = 0; sel < 2; sel++) {
                        const int nf = np * 2 + sel;
                        asm volatile(
                            "mma.sync.aligned.m16n8k16.row.col.f32.f16.f16.f32 "
                            "{%0,%1,%2,%3}, {%4,%5,%6,%7}, {%8,%9}, {%0,%1,%2,%3};"
                            : "+f"(acc[mf][nf][0]), "+f"(acc[mf][nf][1]),
                              "+f"(acc[mf][nf][2]), "+f"(acc[mf][nf][3])
                            : "r"(ar[0]), "r"(ar[1]), "r"(ar[2]), "r"(ar[3]),
                              "r"(bh[np][sel]), "r"(bh[np][2 + sel]));
                    }
                }
            }
        }
        __syncthreads();   // all warps done reading A tile jt

        // --- Prefetch next A tile (overlaps epilogue) ---
        if (jtl < 3) {
            const int j0n = (((jtl + 1) + phase) & 3) * 128;
            #pragma unroll 4
            for (int idx = t; idx < 2048; idx += 128) {
                int row = idx >> 4;
                int c16 = idx & 15;
                uint32_t dst = sb + SM_A + row * LDA + c16 * 16;
                const __half* src = g_ch + ((size_t)b * NC_ + j0n + row) * D_ + c16 * 8;
                asm volatile("cp.async.cg.shared.global [%0], [%1], 16;"
                             :: "r"(dst), "l"(src) : "memory");
            }
        }

        // --- Epilogue: bias + mask, streaming fp32 stores ---
        #pragma unroll
        for (int mf = 0; mf < 4; mf++) {
            const int jl = j0 + wm * 64 + mf * 16 + g;
            const float s0 = scale_s[jl];
            const float s1 = scale_s[jl + 8];
            float* r0p = out + (((size_t)b * NP_ + i) * NC_ + jl) * P_ + wn * 64 + tig * 2;
            float* r1p = r0p + (size_t)8 * P_;
            #pragma unroll
            for (int nf = 0; nf < 8; nf++) {
                const int h = wn * 64 + nf * 8 + tig * 2;
                float x0 = (acc[mf][nf][0] + bias_s[h])     * s0;
                float y0 = (acc[mf][nf][1] + bias_s[h + 1]) * s0;
                float x1 = (acc[mf][nf][2] + bias_s[h])     * s1;
                float y1 = (acc[mf][nf][3] + bias_s[h + 1]) * s1;
                asm volatile("st.global.cs.v2.f32 [%0], {%1, %2};"
                             :: "l"(r0p + nf * 8), "f"(x0), "f"(y0) : "memory");
                asm volatile("st.global.cs.v2.f32 [%0], {%1, %2};"
                             :: "l"(r1p + nf * 8), "f"(x1), "f"(y1) : "memory");
            }
        }

        if (jtl < 3) {
            asm volatile("cp.async.wait_all;" ::: "memory");
            __syncthreads();
        }
    }
}

// ---------------------------------------------------------------------------
// Fallback inter_mask kernel (only for unexpected tail sizes)
// ---------------------------------------------------------------------------
__global__ void mask_float_kernel(const int* __restrict__ p_mask,
                                  const int* __restrict__ c_mask,
                                  float* __restrict__ out, long n) {
    long idx = (long)blockIdx.x * blockDim.x + threadIdx.x;
    if (idx >= n) return;
    int j  = (int)(idx & (NC_ - 1));
    long bi = idx >> 9;
    int i  = (int)(bi & (NP_ - 1));
    int b  = (int)(bi >> 9);
    out[idx] = (p_mask[b * NP_ + i] && c_mask[b * NC_ + j]) ? 1.0f : 0.0f;
}

// ---------------------------------------------------------------------------
extern "C" void kernel_launch(void* const* d_in, const int* in_sizes, int n_in,
                              void* d_out, int out_size) {
    const float* p_embed = (const float*)d_in[0];
    const float* c_embed = (const float*)d_in[1];
    const int*   p_mask  = (const int*)d_in[2];
    const int*   c_mask  = (const int*)d_in[3];
    const float* ln_p_w  = (const float*)d_in[4];
    const float* ln_p_b  = (const float*)d_in[5];
    const float* ln_c_w  = (const float*)d_in[6];
    const float* ln_c_b  = (const float*)d_in[7];
    const float* W_out   = (const float*)d_in[8];
    const float* b_out   = (const float*)d_in[9];
    float* out = (float*)d_out;

    cudaFuncSetAttribute(gemm_mma_kernel,
                         cudaFuncAttributeMaxDynamicSharedMemorySize, SM_TOTAL);

    // LayerNorm (p -> fp32, c -> fp16)
    ln_kernel<<<(B_ * (NP_ + NC_)) / 8, 256>>>(p_embed, c_embed,
                                               ln_p_w, ln_p_b, ln_c_w, ln_c_b);

    // Decide inter_mask tail format
    const long inter_elems = (long)B_ * NP_ * NC_ * P_;
    const long mask_elems  = (long)B_ * NP_ * NC_;
    long extra = (long)out_size - inter_elems;
    void* mask_out = nullptr;
    int mask_mode = 0;
    if (extra >= mask_elems) {
        mask_out = (void*)(out + inter_elems); mask_mode = 1;      // float per entry
    } else if (extra == mask_elems / 4) {
        mask_out = (void*)(out + inter_elems); mask_mode = 2;      // byte per entry
    }

    // Phase-staggered fp16 tensor-core interaction GEMM, 3 CTAs/SM
    dim3 grid(NP_, B_);
    gemm_mma_kernel<<<grid, 128, SM_TOTAL>>>(p_mask, c_mask, W_out, b_out, out,
                                             mask_out, mask_mode);

    // Fallback for odd partial tails only
    if (mask_mode == 0 && extra > 0) {
        long n = extra < mask_elems ? extra : mask_elems;
        mask_float_kernel<<<(int)((n + 255) / 256), 256>>>(
            p_mask, c_mask, out + inter_elems, n);
    }
}